// round 2
// baseline (speedup 1.0000x reference)
#include <cuda_runtime.h>

// conv2d 4096x4096 (fp32) * 15x15 VALID + bias -> 4082x4082 (fp32)
// Direct shared-memory tiled conv, register-blocked 8x2 per thread.
// R1 fix: 16B-align the smem input tile (float4 STS was misaligned because
// sW (900 B) preceded sX in the smem layout).

#define H 4096
#define W 4096
#define KH 15
#define KW 15
#define OH 4082
#define OW 4082

#define BX 128          // output tile width per block
#define BY 32           // output tile height per block
#define TX 16           // threads in x
#define TY 16           // threads in y
#define RX 8            // outputs per thread in x
#define RY 2            // outputs per thread in y

#define IN_W (BX + KW - 1)          // 142
#define IN_H (BY + KH - 1)          // 46
#define SROW 144                    // padded smem row (multiple of 4)

__global__ __launch_bounds__(TX * TY)
void conv2d_tiled_kernel(const float* __restrict__ X,
                         const float* __restrict__ Wt,
                         const float* __restrict__ bias,
                         float* __restrict__ out)
{
    __shared__ __align__(16) float sX[IN_H][SROW];   // declared first, 16B aligned
    __shared__ __align__(16) float sW[KH * KW + 3];  // padded

    const int tid = threadIdx.x;                 // 0..255
    const int bx = blockIdx.x * BX;
    const int by = blockIdx.y * BY;

    // ---- stage weights ----
    if (tid < KH * KW) sW[tid] = Wt[tid];

    // ---- stage input tile: IN_H rows x 144 cols (float4 vectorized, guarded) ----
    // 46 rows * 36 float4 = 1656 vec loads over 256 threads
    const int NV = IN_H * (SROW / 4);
    for (int idx = tid; idx < NV; idx += TX * TY) {
        int r  = idx / (SROW / 4);
        int c4 = idx - r * (SROW / 4);
        int gr = by + r;
        int gc = bx + c4 * 4;
        float4 v = make_float4(0.f, 0.f, 0.f, 0.f);
        if (gr < H) {
            const float* src = X + (long)gr * W + gc;
            if (gc + 3 < W) {
                v = *(const float4*)src;
            } else {
                if (gc + 0 < W) v.x = src[0];
                if (gc + 1 < W) v.y = src[1];
                if (gc + 2 < W) v.z = src[2];
                if (gc + 3 < W) v.w = src[3];
            }
        }
        *(float4*)&sX[r][c4 * 4] = v;
    }
    __syncthreads();

    // ---- compute 8x2 outputs per thread ----
    const int tx = tid & (TX - 1);
    const int ty = tid >> 4;
    const int ox = tx * RX;     // within-tile output col base
    const int oy = ty * RY;     // within-tile output row base

    float acc[RY][RX];
    #pragma unroll
    for (int i = 0; i < RY; ++i)
        #pragma unroll
        for (int j = 0; j < RX; ++j)
            acc[i][j] = 0.f;

    #pragma unroll 1
    for (int ky = 0; ky < KH; ++ky) {
        // load the two input rows this thread needs (22 floats each)
        float xv[RY][RX + KW - 1];
        #pragma unroll
        for (int i = 0; i < RY; ++i) {
            const float* row = &sX[oy + i + ky][ox];
            #pragma unroll
            for (int c = 0; c < RX + KW - 1; ++c)
                xv[i][c] = row[c];
        }
        #pragma unroll
        for (int kx = 0; kx < KW; ++kx) {
            float wv = sW[ky * KW + kx];
            #pragma unroll
            for (int i = 0; i < RY; ++i)
                #pragma unroll
                for (int j = 0; j < RX; ++j)
                    acc[i][j] = fmaf(wv, xv[i][j + kx], acc[i][j]);
        }
    }

    // ---- store (guarded) ----
    const float b0 = bias[0];
    #pragma unroll
    for (int i = 0; i < RY; ++i) {
        int orow = by + oy + i;
        if (orow >= OH) continue;
        #pragma unroll
        for (int j = 0; j < RX; ++j) {
            int ocol = bx + ox + j;
            if (ocol < OW)
                out[(long)orow * OW + ocol] = acc[i][j] + b0;
        }
    }
}

extern "C" void kernel_launch(void* const* d_in, const int* in_sizes, int n_in,
                              void* d_out, int out_size)
{
    const float* X  = (const float*)d_in[0];
    const float* Wt = (const float*)d_in[1];
    const float* bs = (const float*)d_in[2];
    float* out = (float*)d_out;

    dim3 grid((OW + BX - 1) / BX, (OH + BY - 1) / BY);   // 32 x 128
    dim3 block(TX * TY);
    conv2d_tiled_kernel<<<grid, block>>>(X, Wt, bs, out);
}

// round 3
// speedup vs baseline: 1.0840x; 1.0840x over previous
#include <cuda_runtime.h>

// conv2d 4096x4096 (fp32) * 15x15 VALID + bias -> 4082x4082 (fp32)
// R2: packed fma.rn.f32x2 (2x fp32 FMA rate) + explicit float4 LDS (conflict-free).

#define H 4096
#define W 4096
#define KH 15
#define KW 15
#define OH 4082
#define OW 4082

#define BX 128          // output tile width per block
#define BY 32           // output tile height per block
#define NT 256          // threads per block
#define RX 8            // outputs per thread in x (4 packed pairs)
#define RY 2            // outputs per thread in y

#define IN_H (BY + KH - 1)          // 46
#define SROW 144                    // padded smem row (multiple of 4)

typedef unsigned long long ull;

__device__ __forceinline__ ull pack2(float lo, float hi) {
    ull r;
    asm("mov.b64 %0, {%1, %2};" : "=l"(r) : "f"(lo), "f"(hi));
    return r;
}
__device__ __forceinline__ void unpack2(ull v, float& lo, float& hi) {
    asm("mov.b64 {%0, %1}, %2;" : "=f"(lo), "=f"(hi) : "l"(v));
}
__device__ __forceinline__ ull fma2(ull a, ull b, ull c) {
    ull d;
    asm("fma.rn.f32x2 %0, %1, %2, %3;" : "=l"(d) : "l"(a), "l"(b), "l"(c));
    return d;
}

__global__ __launch_bounds__(NT, 2)
void conv2d_f32x2_kernel(const float* __restrict__ X,
                         const float* __restrict__ Wt,
                         const float* __restrict__ bias,
                         float* __restrict__ out)
{
    __shared__ __align__(16) float sX[IN_H][SROW];
    __shared__ __align__(16) float sW[KH * 16];   // rows padded to 16 for float4 loads

    const int tid = threadIdx.x;
    const int bx = blockIdx.x * BX;
    const int by = blockIdx.y * BY;

    // ---- stage weights (row-padded to 16) ----
    if (tid < KH * 16) {
        int r = tid >> 4, c = tid & 15;
        sW[tid] = (c < KW) ? Wt[r * KW + c] : 0.f;
    }

    // ---- stage input tile: 46 rows x 144 cols, float4, guarded ----
    const int NV = IN_H * (SROW / 4);
    for (int idx = tid; idx < NV; idx += NT) {
        int r  = idx / (SROW / 4);
        int c4 = idx - r * (SROW / 4);
        int gr = by + r;
        int gc = bx + c4 * 4;
        float4 v = make_float4(0.f, 0.f, 0.f, 0.f);
        if (gr < H) {
            const float* src = X + (long)gr * W + gc;
            if (gc + 3 < W) v = *(const float4*)src;
            else {
                if (gc + 0 < W) v.x = src[0];
                if (gc + 1 < W) v.y = src[1];
                if (gc + 2 < W) v.z = src[2];
                if (gc + 3 < W) v.w = src[3];
            }
        }
        *(float4*)&sX[r][c4 * 4] = v;
    }
    __syncthreads();

    const int tx = tid & 15;
    const int ty = tid >> 4;
    const int ox = tx * RX;     // 32B aligned in smem
    const int oy = ty * RY;

    ull acc[RY][4];
    #pragma unroll
    for (int i = 0; i < RY; ++i)
        #pragma unroll
        for (int j = 0; j < 4; ++j)
            acc[i][j] = pack2(0.f, 0.f);

    #pragma unroll 1
    for (int ky = 0; ky < KH; ++ky) {
        // broadcast weights for this ky: 4 uniform float4 loads + packs
        const float4 w0 = *(const float4*)&sW[ky * 16 + 0];
        const float4 w1 = *(const float4*)&sW[ky * 16 + 4];
        const float4 w2 = *(const float4*)&sW[ky * 16 + 8];
        const float4 w3 = *(const float4*)&sW[ky * 16 + 12];
        ull w2k[KW];
        w2k[ 0]=pack2(w0.x,w0.x); w2k[ 1]=pack2(w0.y,w0.y); w2k[ 2]=pack2(w0.z,w0.z); w2k[ 3]=pack2(w0.w,w0.w);
        w2k[ 4]=pack2(w1.x,w1.x); w2k[ 5]=pack2(w1.y,w1.y); w2k[ 6]=pack2(w1.z,w1.z); w2k[ 7]=pack2(w1.w,w1.w);
        w2k[ 8]=pack2(w2.x,w2.x); w2k[ 9]=pack2(w2.y,w2.y); w2k[10]=pack2(w2.z,w2.z); w2k[11]=pack2(w2.w,w2.w);
        w2k[12]=pack2(w3.x,w3.x); w2k[13]=pack2(w3.y,w3.y); w2k[14]=pack2(w3.z,w3.z);

        #pragma unroll
        for (int i = 0; i < RY; ++i) {
            const float* row = &sX[oy + i + ky][ox];
            const float4 v0 = *(const float4*)(row +  0);
            const float4 v1 = *(const float4*)(row +  4);
            const float4 v2 = *(const float4*)(row +  8);
            const float4 v3 = *(const float4*)(row + 12);
            const float4 v4 = *(const float4*)(row + 16);
            const float4 v5 = *(const float4*)(row + 20);

            // even pairs P[p] = (x[2p], x[2p+1]), p=0..10
            ull P[11];
            P[0]=pack2(v0.x,v0.y); P[1] =pack2(v0.z,v0.w);
            P[2]=pack2(v1.x,v1.y); P[3] =pack2(v1.z,v1.w);
            P[4]=pack2(v2.x,v2.y); P[5] =pack2(v2.z,v2.w);
            P[6]=pack2(v3.x,v3.y); P[7] =pack2(v3.z,v3.w);
            P[8]=pack2(v4.x,v4.y); P[9] =pack2(v4.z,v4.w);
            P[10]=pack2(v5.x,v5.y);
            // odd pairs O[p] = (x[2p+1], x[2p+2]), p=0..9
            ull O[10];
            O[0]=pack2(v0.y,v0.z); O[1]=pack2(v0.w,v1.x);
            O[2]=pack2(v1.y,v1.z); O[3]=pack2(v1.w,v2.x);
            O[4]=pack2(v2.y,v2.z); O[5]=pack2(v2.w,v3.x);
            O[6]=pack2(v3.y,v3.z); O[7]=pack2(v3.w,v4.x);
            O[8]=pack2(v4.y,v4.z); O[9]=pack2(v4.w,v5.x);

            // kx = 2a (even) uses P[j+a]; kx = 2a+1 (odd) uses O[j+a]
            #pragma unroll
            for (int a = 0; a < 8; ++a) {
                #pragma unroll
                for (int j = 0; j < 4; ++j)
                    acc[i][j] = fma2(w2k[2 * a], P[j + a], acc[i][j]);
                if (a < 7) {
                    #pragma unroll
                    for (int j = 0; j < 4; ++j)
                        acc[i][j] = fma2(w2k[2 * a + 1], O[j + a], acc[i][j]);
                }
            }
        }
    }

    // ---- epilogue: bias + guarded float2 stores ----
    const float b0 = bias[0];
    #pragma unroll
    for (int i = 0; i < RY; ++i) {
        int orow = by + oy + i;
        if (orow >= OH) continue;
        #pragma unroll
        for (int j = 0; j < 4; ++j) {
            int ocol = bx + ox + 2 * j;        // even; OW even -> pair fully in/out
            if (ocol < OW) {
                float lo, hi;
                unpack2(acc[i][j], lo, hi);
                float2 st = make_float2(lo + b0, hi + b0);
                *(float2*)(out + (long)orow * OW + ocol) = st;
            }
        }
    }
}

extern "C" void kernel_launch(void* const* d_in, const int* in_sizes, int n_in,
                              void* d_out, int out_size)
{
    const float* X  = (const float*)d_in[0];
    const float* Wt = (const float*)d_in[1];
    const float* bs = (const float*)d_in[2];
    float* out = (float*)d_out;

    dim3 grid((OW + BX - 1) / BX, (OH + BY - 1) / BY);   // 32 x 128
    conv2d_f32x2_kernel<<<grid, NT>>>(X, Wt, bs, out);
}